// round 1
// baseline (speedup 1.0000x reference)
#include <cuda_runtime.h>
#include <cstdint>

// Problem dims (fixed)
#define LQ 2048
#define BB 8
#define DD 768
#define MROWS (BB * LQ)            // 16384 flattened (b, l) rows
#define QKSCALE 0.0360843918243516f // 1/sqrt(768)

// ---------------------------------------------------------------------------
// Scratch (device globals: allocation-free per harness rules)
// ---------------------------------------------------------------------------
__device__ float g_S[(size_t)BB * LQ * LQ];     // 128 MB: attention logits/probs (reused per branch)
__device__ float g_ctx[(size_t)MROWS * DD];     // 48 MB: attention context (reused per branch)
__device__ float g_ya[(size_t)MROWS * DD];      // 48 MB: branch-a conv output
__device__ float g_yv[(size_t)MROWS * DD];      // 48 MB: branch-v conv output
__device__ float g_part[2 * 128 * DD];          // BN partial sums [sum | sumsq] per 128-row block
__device__ float g_stats[2 * 2 * DD];           // per branch: [scale(768) | shift(768)]

// ---------------------------------------------------------------------------
// Tiled fp32 GEMM:  C[m,n] = alpha * sum_k A(m,k) * B(k,n)
//   A(m,k)  at A[m*lda + k]                      (always k-contiguous)
//   B(k,n)  at B[n*ldbn + k]  if BKC (k-contig)
//           at B[k*ldbk + n]  else   (n-contig)
// Tiles: BM=BN=128, BK=16, 256 threads, 8x8 per thread. Dims divide tiles.
// ---------------------------------------------------------------------------
template<bool BKC>
__global__ __launch_bounds__(256, 2)
void gemm_tile(const float* __restrict__ A, const float* __restrict__ Bm,
               float* __restrict__ C,
               int K, int lda, int ldbn, int ldbk, int ldc,
               long strideA, long strideB, long strideC, float alpha)
{
    __shared__ float As[16][132];
    __shared__ float Bs[16][132];

    A  += (size_t)strideA * blockIdx.z;
    Bm += (size_t)strideB * blockIdx.z;
    C  += (size_t)strideC * blockIdx.z;

    const int m0 = blockIdx.y * 128;
    const int n0 = blockIdx.x * 128;
    const int t  = threadIdx.x;
    const int tx = t & 15;          // 0..15 -> n micro-tile
    const int ty = t >> 4;          // 0..15 -> m micro-tile

    float acc[8][8];
#pragma unroll
    for (int i = 0; i < 8; i++)
#pragma unroll
        for (int j = 0; j < 8; j++) acc[i][j] = 0.f;

    for (int k0 = 0; k0 < K; k0 += 16) {
        // Stage A tile (k-contiguous global loads, transposed smem store)
#pragma unroll
        for (int i = 0; i < 8; i++) {
            int idx = t + i * 256;
            int k = idx & 15, m = idx >> 4;
            As[k][m] = A[(size_t)(m0 + m) * lda + k0 + k];
        }
        // Stage B tile
        if (BKC) {
#pragma unroll
            for (int i = 0; i < 8; i++) {
                int idx = t + i * 256;
                int k = idx & 15, n = idx >> 4;
                Bs[k][n] = Bm[(size_t)(n0 + n) * ldbn + k0 + k];
            }
        } else {
#pragma unroll
            for (int i = 0; i < 8; i++) {
                int idx = t + i * 256;
                int n = idx & 127, k = idx >> 7;
                Bs[k][n] = Bm[(size_t)(k0 + k) * ldbk + n0 + n];
            }
        }
        __syncthreads();

#pragma unroll
        for (int k = 0; k < 16; k++) {
            float4 a0 = *(const float4*)&As[k][ty * 8];
            float4 a1 = *(const float4*)&As[k][ty * 8 + 4];
            float4 b0 = *(const float4*)&Bs[k][tx * 8];
            float4 b1 = *(const float4*)&Bs[k][tx * 8 + 4];
            float av[8] = {a0.x, a0.y, a0.z, a0.w, a1.x, a1.y, a1.z, a1.w};
            float bv[8] = {b0.x, b0.y, b0.z, b0.w, b1.x, b1.y, b1.z, b1.w};
#pragma unroll
            for (int i = 0; i < 8; i++)
#pragma unroll
                for (int j = 0; j < 8; j++)
                    acc[i][j] += av[i] * bv[j];
        }
        __syncthreads();
    }

#pragma unroll
    for (int i = 0; i < 8; i++) {
        float* cr = C + (size_t)(m0 + ty * 8 + i) * ldc + n0 + tx * 8;
        float4 o0 = make_float4(acc[i][0] * alpha, acc[i][1] * alpha,
                                acc[i][2] * alpha, acc[i][3] * alpha);
        float4 o1 = make_float4(acc[i][4] * alpha, acc[i][5] * alpha,
                                acc[i][6] * alpha, acc[i][7] * alpha);
        ((float4*)cr)[0] = o0;
        ((float4*)cr)[1] = o1;
    }
}

// ---------------------------------------------------------------------------
// In-place row softmax over 2048-wide rows. grid = 16384, block = 256.
// ---------------------------------------------------------------------------
__global__ void softmax_rows(float* __restrict__ S)
{
    __shared__ float red[8];
    float* p = S + (size_t)blockIdx.x * 2048;
    const int t = threadIdx.x;

    float4 v0 = ((const float4*)p)[t];
    float4 v1 = ((const float4*)p)[t + 256];

    float m = fmaxf(fmaxf(fmaxf(v0.x, v0.y), fmaxf(v0.z, v0.w)),
                    fmaxf(fmaxf(v1.x, v1.y), fmaxf(v1.z, v1.w)));
#pragma unroll
    for (int o = 16; o; o >>= 1) m = fmaxf(m, __shfl_xor_sync(~0u, m, o));
    if ((t & 31) == 0) red[t >> 5] = m;
    __syncthreads();
    float mx = red[0];
#pragma unroll
    for (int w = 1; w < 8; w++) mx = fmaxf(mx, red[w]);
    __syncthreads();

    v0.x = __expf(v0.x - mx); v0.y = __expf(v0.y - mx);
    v0.z = __expf(v0.z - mx); v0.w = __expf(v0.w - mx);
    v1.x = __expf(v1.x - mx); v1.y = __expf(v1.y - mx);
    v1.z = __expf(v1.z - mx); v1.w = __expf(v1.w - mx);

    float s = v0.x + v0.y + v0.z + v0.w + v1.x + v1.y + v1.z + v1.w;
#pragma unroll
    for (int o = 16; o; o >>= 1) s += __shfl_xor_sync(~0u, s, o);
    if ((t & 31) == 0) red[t >> 5] = s;
    __syncthreads();
    float sm = 0.f;
#pragma unroll
    for (int w = 0; w < 8; w++) sm += red[w];
    float inv = 1.f / sm;

    v0.x *= inv; v0.y *= inv; v0.z *= inv; v0.w *= inv;
    v1.x *= inv; v1.y *= inv; v1.z *= inv; v1.w *= inv;
    ((float4*)p)[t]       = v0;
    ((float4*)p)[t + 256] = v1;
}

// ---------------------------------------------------------------------------
// BN stats stage 1: per-128-row-block partial channel sums. grid=128, block=256.
// ---------------------------------------------------------------------------
__global__ void bn_partial(const float* __restrict__ y, float* __restrict__ part)
{
    const int t = threadIdx.x;
    const float* base = y + (size_t)blockIdx.x * 128 * DD;
    float s[3] = {0.f, 0.f, 0.f}, q[3] = {0.f, 0.f, 0.f};
    for (int r = 0; r < 128; r++) {
        const float* row = base + (size_t)r * DD;
#pragma unroll
        for (int j = 0; j < 3; j++) {
            float v = row[t + j * 256];
            s[j] += v; q[j] += v * v;
        }
    }
#pragma unroll
    for (int j = 0; j < 3; j++) {
        part[blockIdx.x * DD + t + j * 256] = s[j];
        part[128 * DD + blockIdx.x * DD + t + j * 256] = q[j];
    }
}

// ---------------------------------------------------------------------------
// BN stats stage 2: finalize per-channel scale/shift. grid=3, block=256.
// (Conv bias omitted everywhere: it cancels exactly in BN mean subtraction.)
// ---------------------------------------------------------------------------
__global__ void bn_finalize(const float* __restrict__ part,
                            const float* __restrict__ gamma,
                            const float* __restrict__ beta,
                            float* __restrict__ statsOut)
{
    const int c = blockIdx.x * 256 + threadIdx.x;
    float s = 0.f, q = 0.f;
    for (int k = 0; k < 128; k++) {
        s += part[k * DD + c];
        q += part[128 * DD + k * DD + c];
    }
    const float mean = s * (1.f / (float)MROWS);
    const float var  = q * (1.f / (float)MROWS) - mean * mean;
    const float scale = gamma[c] * rsqrtf(var + 1e-5f);
    statsOut[c]      = scale;
    statsOut[DD + c] = beta[c] - mean * scale;
}

// ---------------------------------------------------------------------------
// Combine: BN-apply + PReLU (both branches) + residual + LayerNorm.
// grid = 16384 positions (pos = b*2048 + l), block = 256 (3 channels/thread).
// ---------------------------------------------------------------------------
__global__ void combine_ln(const float* __restrict__ x,
                           const float* __restrict__ ya,
                           const float* __restrict__ yv,
                           const float* __restrict__ stats,
                           const float* __restrict__ pa,
                           const float* __restrict__ pv,
                           const float* __restrict__ lng,
                           const float* __restrict__ lnb,
                           float* __restrict__ out)
{
    __shared__ float rs[8], rq[8];
    const int pos = blockIdx.x;
    const int b = pos >> 11, l = pos & 2047;
    const size_t yoff = (size_t)pos * DD;
    const size_t xoff = (size_t)l * (BB * DD) + (size_t)b * DD;
    const int t = threadIdx.x;
    const float aa = pa[0], av = pv[0];

    float vv[3];
    float s = 0.f, q = 0.f;
#pragma unroll
    for (int j = 0; j < 3; j++) {
        const int d = t + j * 256;
        float va = ya[yoff + d] * stats[d] + stats[DD + d];
        va = va > 0.f ? va : aa * va;
        float vb = yv[yoff + d] * stats[2 * DD + d] + stats[3 * DD + d];
        vb = vb > 0.f ? vb : av * vb;
        float val = x[xoff + d] + va + vb;
        vv[j] = val; s += val; q += val * val;
    }
#pragma unroll
    for (int o = 16; o; o >>= 1) {
        s += __shfl_xor_sync(~0u, s, o);
        q += __shfl_xor_sync(~0u, q, o);
    }
    if ((t & 31) == 0) { rs[t >> 5] = s; rq[t >> 5] = q; }
    __syncthreads();
    s = 0.f; q = 0.f;
#pragma unroll
    for (int w = 0; w < 8; w++) { s += rs[w]; q += rq[w]; }
    const float mean = s * (1.f / (float)DD);
    const float var  = q * (1.f / (float)DD) - mean * mean;
    const float rstd = rsqrtf(var + 1e-5f);
#pragma unroll
    for (int j = 0; j < 3; j++) {
        const int d = t + j * 256;
        out[xoff + d] = (vv[j] - mean) * rstd * lng[d] + lnb[d];
    }
}

// ---------------------------------------------------------------------------
// Host orchestration (graph-capturable: kernel launches only)
// ---------------------------------------------------------------------------
extern "C" void kernel_launch(void* const* d_in, const int* in_sizes, int n_in,
                              void* d_out, int out_size)
{
    const float* x_a    = (const float*)d_in[0];
    const float* x_v    = (const float*)d_in[1];
    const float* x      = (const float*)d_in[2];
    const float* W_a    = (const float*)d_in[3];
    // d_in[4] = b_a (bias) — cancels in BatchNorm, unused
    const float* bn_a_g = (const float*)d_in[5];
    const float* bn_a_b = (const float*)d_in[6];
    const float* pre_a  = (const float*)d_in[7];
    const float* W_v    = (const float*)d_in[8];
    // d_in[9] = b_v — unused (cancels in BN)
    const float* bn_v_g = (const float*)d_in[10];
    const float* bn_v_b = (const float*)d_in[11];
    const float* pre_v  = (const float*)d_in[12];
    const float* ln_g   = (const float*)d_in[13];
    const float* ln_b   = (const float*)d_in[14];
    float* out = (float*)d_out;

    float *S, *ctx, *ya, *yv, *part, *stats;
    cudaGetSymbolAddress((void**)&S,     g_S);
    cudaGetSymbolAddress((void**)&ctx,   g_ctx);
    cudaGetSymbolAddress((void**)&ya,    g_ya);
    cudaGetSymbolAddress((void**)&yv,    g_yv);
    cudaGetSymbolAddress((void**)&part,  g_part);
    cudaGetSymbolAddress((void**)&stats, g_stats);

    const long sBL = (size_t)LQ * LQ;       // per-batch logits stride
    const long sCT = (size_t)LQ * DD;       // per-batch ctx stride

    for (int br = 0; br < 2; br++) {
        const float* kv    = (br == 0) ? x_a    : x_v;
        const float* W     = (br == 0) ? W_a    : W_v;
        const float* bng   = (br == 0) ? bn_a_g : bn_v_g;
        const float* bnb   = (br == 0) ? bn_a_b : bn_v_b;
        float*       y     = (br == 0) ? ya     : yv;
        float*       st    = stats + br * 2 * DD;

        // 1) S[b,i,j] = scale * sum_d q(b,i,d) * kv(b,j,d)
        //    q(b,i,d) = x[i*6144 + b*768 + d]   (batch offset 768, row stride 6144)
        gemm_tile<true><<<dim3(LQ / 128, LQ / 128, BB), 256>>>(
            x, kv, S,
            /*K=*/DD, /*lda=*/BB * DD, /*ldbn=*/BB * DD, /*ldbk=*/0, /*ldc=*/LQ,
            /*strideA=*/DD, /*strideB=*/DD, /*strideC=*/sBL, QKSCALE);

        // 2) softmax over j for each (b,i)
        softmax_rows<<<MROWS, 256>>>(S);

        // 3) ctx[b,i,d] = sum_j P[b,i,j] * kv(b,j,d)
        gemm_tile<false><<<dim3(DD / 128, LQ / 128, BB), 256>>>(
            S, kv, ctx,
            /*K=*/LQ, /*lda=*/LQ, /*ldbn=*/0, /*ldbk=*/BB * DD, /*ldc=*/DD,
            /*strideA=*/sBL, /*strideB=*/DD, /*strideC=*/sCT, 1.f);

        // 4) y[r,e] = sum_d ctx[r,d] * W[e,d]   (flat M = 16384; bias skipped)
        gemm_tile<true><<<dim3(DD / 128, MROWS / 128, 1), 256>>>(
            ctx, W, y,
            /*K=*/DD, /*lda=*/DD, /*ldbn=*/DD, /*ldbk=*/0, /*ldc=*/DD,
            0, 0, 0, 1.f);

        // 5-6) BatchNorm stats (deterministic two-stage) -> per-channel scale/shift
        bn_partial<<<128, 256>>>(y, part);
        bn_finalize<<<3, 256>>>(part, bng, bnb, st);
    }

    // 7) BN-apply + PReLU + residual + LayerNorm, write [L, B, D] output
    combine_ln<<<MROWS, 256>>>(x, ya, yv, stats, pre_a, pre_v, ln_g, ln_b, out);
}

// round 3
// speedup vs baseline: 2.9187x; 2.9187x over previous
#include <cuda_runtime.h>
#include <cuda_bf16.h>
#include <cstdint>

#define LQ 2048
#define BB 8
#define DD 768
#define MROWS (BB * LQ)
#define QKSCALE 0.0360843918243516f

using bf16 = __nv_bfloat16;

// ---------------------------------------------------------------------------
// Scratch (device globals; allocation-free per harness rules)
// ---------------------------------------------------------------------------
__device__ __align__(16) float g_S[(size_t)BB * LQ * LQ];     // 128MB logits (reused per branch)
__device__ __align__(16) bf16  g_Phi[(size_t)BB * LQ * LQ];   // 64MB softmax hi
__device__ __align__(16) bf16  g_Plo[(size_t)BB * LQ * LQ];   // 64MB softmax lo
__device__ __align__(16) bf16  g_qhi[(size_t)MROWS * DD], g_qlo[(size_t)MROWS * DD];
__device__ __align__(16) bf16  g_kvhi[(size_t)MROWS * DD], g_kvlo[(size_t)MROWS * DD];
__device__ __align__(16) bf16  g_kThi[(size_t)MROWS * DD], g_kTlo[(size_t)MROWS * DD];
__device__ __align__(16) bf16  g_chi[(size_t)MROWS * DD], g_clo[(size_t)MROWS * DD];
__device__ __align__(16) bf16  g_Whi[2 * DD * DD], g_Wlo[2 * DD * DD];
__device__ __align__(16) float g_ya[(size_t)MROWS * DD], g_yv[(size_t)MROWS * DD];
__device__ float g_part[2 * 128 * DD];
__device__ float g_stats[2 * 2 * DD];

// ---------------------------------------------------------------------------
// Helpers (baseline PTX only: ldmatrix / mma.sync / cp.async — no tcgen05)
// ---------------------------------------------------------------------------
__device__ __forceinline__ uint32_t smem_u32(const void* p) {
    uint32_t a;
    asm("{ .reg .u64 t; cvta.to.shared.u64 t, %1; cvt.u32.u64 %0, t; }" : "=r"(a) : "l"(p));
    return a;
}

__device__ __forceinline__ void cp16(uint32_t saddr, const void* gaddr) {
    asm volatile("cp.async.cg.shared.global [%0], [%1], 16;" :: "r"(saddr), "l"(gaddr));
}
#define CP_COMMIT() asm volatile("cp.async.commit_group;" ::: "memory")
#define CP_WAIT0()  asm volatile("cp.async.wait_group 0;" ::: "memory")

__device__ __forceinline__ void ldmat_x4(uint32_t& r0, uint32_t& r1, uint32_t& r2,
                                         uint32_t& r3, uint32_t addr) {
    asm volatile("ldmatrix.sync.aligned.m8n8.x4.shared.b16 {%0,%1,%2,%3}, [%4];"
                 : "=r"(r0), "=r"(r1), "=r"(r2), "=r"(r3) : "r"(addr));
}
__device__ __forceinline__ void ldmat_x2(uint32_t& r0, uint32_t& r1, uint32_t addr) {
    asm volatile("ldmatrix.sync.aligned.m8n8.x2.shared.b16 {%0,%1}, [%2];"
                 : "=r"(r0), "=r"(r1) : "r"(addr));
}
__device__ __forceinline__ void mma16816(float* c, uint32_t a0, uint32_t a1,
                                         uint32_t a2, uint32_t a3,
                                         uint32_t b0, uint32_t b1) {
    asm volatile(
        "mma.sync.aligned.m16n8k16.row.col.f32.bf16.bf16.f32 "
        "{%0,%1,%2,%3}, {%4,%5,%6,%7}, {%8,%9}, {%0,%1,%2,%3};"
        : "+f"(c[0]), "+f"(c[1]), "+f"(c[2]), "+f"(c[3])
        : "r"(a0), "r"(a1), "r"(a2), "r"(a3), "r"(b0), "r"(b1));
}

// SW128 swizzle for 128-byte rows (64 bf16)
__device__ __forceinline__ uint32_t sw_off(int row, int kbyte) {
    uint32_t off = (uint32_t)row * 128u + (uint32_t)kbyte;
    return off ^ ((off >> 3) & 0x70u);
}

__device__ __forceinline__ void split1(float v, uint16_t& h, uint16_t& l) {
    bf16 hb = __float2bfloat16(v);
    h = __bfloat16_as_ushort(hb);
    l = __bfloat16_as_ushort(__float2bfloat16(v - __bfloat162float(hb)));
}
__device__ __forceinline__ uint32_t pack_hi(float a, float b) {
    uint16_t ha, la, hb, lb; split1(a, ha, la); split1(b, hb, lb);
    return (uint32_t)ha | ((uint32_t)hb << 16);
}
__device__ __forceinline__ uint32_t pack_lo(float a, float b) {
    uint16_t ha, la, hb, lb; split1(a, ha, la); split1(b, hb, lb);
    return (uint32_t)la | ((uint32_t)lb << 16);
}

// ---------------------------------------------------------------------------
// Split-bf16 warp-MMA GEMM: C[m,n] = alpha * sum_k A[m,k]*B[n,k]
// A,B k-contiguous. Tile 128x128, K staged in 64-chunks, cp.async 2-stage.
// 8 warps: warp (wm in 0..1, wn in 0..3) owns 64x32 of the tile.
// OUTMODE 0: fp32 C.  OUTMODE 1: split-bf16 C (Chi/Clo).
// ---------------------------------------------------------------------------
#define STAGE_BYTES 65536
#define GEMM_SMEM (2 * STAGE_BYTES)

__device__ __forceinline__ void stage_load(uint32_t sdst, const bf16* __restrict__ Ahi,
                                           const bf16* __restrict__ Alo,
                                           const bf16* __restrict__ Bhi,
                                           const bf16* __restrict__ Blo,
                                           int K, int k0, int t) {
    // each tile: 128 rows x 64 bf16 (128B swizzled rows); 4 tiles per stage
#pragma unroll
    for (int i = 0; i < 4; i++) {
        int idx = t + i * 256;           // 0..1023
        int row = idx >> 3, ch = idx & 7; // ch: 16B chunk within row
        uint32_t so = sw_off(row, ch * 16);
        const bf16* g = Ahi + (size_t)row * K + k0 + ch * 8;
        cp16(sdst + so, g);
        cp16(sdst + 16384 + so, Alo + (size_t)row * K + k0 + ch * 8);
        cp16(sdst + 32768 + so, Bhi + (size_t)row * K + k0 + ch * 8);
        cp16(sdst + 49152 + so, Blo + (size_t)row * K + k0 + ch * 8);
    }
}

template<int OUTMODE>
__global__ void __launch_bounds__(256, 1)
mma_gemm(const bf16* __restrict__ Ahi, const bf16* __restrict__ Alo,
         const bf16* __restrict__ Bhi, const bf16* __restrict__ Blo,
         float* __restrict__ C, bf16* __restrict__ Chi, bf16* __restrict__ Clo,
         int K, int ldc, long sA, long sB, long sC, float alpha)
{
    extern __shared__ __align__(1024) char smem[];
    const uint32_t sb = smem_u32(smem);
    const int t = threadIdx.x, lane = t & 31, wid = t >> 5;
    const int wm = wid & 1, wn = wid >> 1;
    const int m0 = blockIdx.y * 128, n0 = blockIdx.x * 128, z = blockIdx.z;
    const int kiters = K >> 6;

    Ahi += (size_t)z * sA + (size_t)m0 * K;
    Alo += (size_t)z * sA + (size_t)m0 * K;
    Bhi += (size_t)z * sB + (size_t)n0 * K;
    Blo += (size_t)z * sB + (size_t)n0 * K;

    float acc[4][4][4];
#pragma unroll
    for (int i = 0; i < 4; i++)
#pragma unroll
        for (int j = 0; j < 4; j++)
#pragma unroll
            for (int q = 0; q < 4; q++) acc[i][j][q] = 0.f;

    // per-lane ldmatrix address components
    const int a_rin = lane & 7;
    const int a_m_add = a_rin + ((lane >> 3) & 1) * 8;   // + m_base
    const int a_k_add = ((lane >> 4) & 1) * 8;           // + k16base
    const int b_rin = lane & 15;                          // lanes 0..15 meaningful
    const int b_n_add = b_rin & 7;
    const int b_k_add = (b_rin >> 3) * 8;

    stage_load(sb, Ahi, Alo, Bhi, Blo, K, 0, t);
    CP_COMMIT();

    for (int it = 0; it < kiters; it++) {
        CP_WAIT0();
        __syncthreads();
        const uint32_t st = sb + (uint32_t)(it & 1) * STAGE_BYTES;
        if (it + 1 < kiters) {
            stage_load(sb + (uint32_t)((it + 1) & 1) * STAGE_BYTES,
                       Ahi, Alo, Bhi, Blo, K, (it + 1) << 6, t);
            CP_COMMIT();
        }

#pragma unroll
        for (int ks = 0; ks < 4; ks++) {
            const int kb = ks * 16;
            uint32_t ah[4][4], al[4][4];
#pragma unroll
            for (int tm = 0; tm < 4; tm++) {
                int m = wm * 64 + tm * 16 + a_m_add;
                uint32_t so = sw_off(m, (kb + a_k_add) * 2);
                ldmat_x4(ah[tm][0], ah[tm][1], ah[tm][2], ah[tm][3], st + so);
                ldmat_x4(al[tm][0], al[tm][1], al[tm][2], al[tm][3], st + 16384 + so);
            }
            uint32_t bh[4][2], bl[4][2];
#pragma unroll
            for (int tn = 0; tn < 4; tn++) {
                int n = wn * 32 + tn * 8 + b_n_add;
                uint32_t so = sw_off(n, (kb + b_k_add) * 2);
                ldmat_x2(bh[tn][0], bh[tn][1], st + 32768 + so);
                ldmat_x2(bl[tn][0], bl[tn][1], st + 49152 + so);
            }
#pragma unroll
            for (int tm = 0; tm < 4; tm++)
#pragma unroll
                for (int tn = 0; tn < 4; tn++) {
                    mma16816(acc[tm][tn], ah[tm][0], ah[tm][1], ah[tm][2], ah[tm][3],
                             bh[tn][0], bh[tn][1]);
                    mma16816(acc[tm][tn], ah[tm][0], ah[tm][1], ah[tm][2], ah[tm][3],
                             bl[tn][0], bl[tn][1]);
                    mma16816(acc[tm][tn], al[tm][0], al[tm][1], al[tm][2], al[tm][3],
                             bh[tn][0], bh[tn][1]);
                }
        }
        __syncthreads();
    }

    // Epilogue
    const int gid = lane >> 2, tig = lane & 3;
#pragma unroll
    for (int tm = 0; tm < 4; tm++) {
        const int r0 = m0 + wm * 64 + tm * 16 + gid;
#pragma unroll
        for (int tn = 0; tn < 4; tn++) {
            const int cN = n0 + wn * 32 + tn * 8 + tig * 2;
            float* a = acc[tm][tn];
            if (OUTMODE == 0) {
                float2 u = make_float2(a[0] * alpha, a[1] * alpha);
                float2 v = make_float2(a[2] * alpha, a[3] * alpha);
                *(float2*)(C + (size_t)z * sC + (size_t)r0 * ldc + cN) = u;
                *(float2*)(C + (size_t)z * sC + (size_t)(r0 + 8) * ldc + cN) = v;
            } else {
                *(uint32_t*)(Chi + (size_t)z * sC + (size_t)r0 * ldc + cN) = pack_hi(a[0], a[1]);
                *(uint32_t*)(Clo + (size_t)z * sC + (size_t)r0 * ldc + cN) = pack_lo(a[0], a[1]);
                *(uint32_t*)(Chi + (size_t)z * sC + (size_t)(r0 + 8) * ldc + cN) = pack_hi(a[2], a[3]);
                *(uint32_t*)(Clo + (size_t)z * sC + (size_t)(r0 + 8) * ldc + cN) = pack_lo(a[2], a[3]);
            }
        }
    }
}

// ---------------------------------------------------------------------------
// Conversions (fp32 -> split bf16) with layout repack
// ---------------------------------------------------------------------------
__global__ void split_lbd_bld(const float* __restrict__ in, bf16* __restrict__ hi,
                              bf16* __restrict__ lo)
{
    const int l = blockIdx.x, b = blockIdx.y, t = threadIdx.x;
    const float* s = in + (size_t)l * (BB * DD) + (size_t)b * DD;
    const size_t o = ((size_t)b * LQ + l) * DD;
#pragma unroll
    for (int j = 0; j < 3; j++) {
        float v = s[t + j * 256];
        bf16 h = __float2bfloat16(v);
        hi[o + t + j * 256] = h;
        lo[o + t + j * 256] = __float2bfloat16(v - __bfloat162float(h));
    }
}

__global__ void split_plain(const float* __restrict__ in, bf16* __restrict__ hi,
                            bf16* __restrict__ lo)
{
    const int i = blockIdx.x * 256 + threadIdx.x;
    float v = in[i];
    bf16 h = __float2bfloat16(v);
    hi[i] = h;
    lo[i] = __float2bfloat16(v - __bfloat162float(h));
}

// [L,B,D] -> [B,D,L] transpose + split
__global__ void split_transpose(const float* __restrict__ in, bf16* __restrict__ thi,
                                bf16* __restrict__ tlo)
{
    __shared__ float tile[32][33];
    const int b = blockIdx.z;
    const int d0 = blockIdx.x * 32, l0 = blockIdx.y * 32;
    const int tx = threadIdx.x, ty = threadIdx.y;
#pragma unroll
    for (int r = 0; r < 4; r++) {
        int l = l0 + ty + r * 8;
        tile[ty + r * 8][tx] = in[(size_t)l * (BB * DD) + (size_t)b * DD + d0 + tx];
    }
    __syncthreads();
#pragma unroll
    for (int r = 0; r < 4; r++) {
        int d = d0 + ty + r * 8;
        float v = tile[tx][ty + r * 8];
        size_t o = ((size_t)b * DD + d) * LQ + l0 + tx;
        bf16 h = __float2bfloat16(v);
        thi[o] = h;
        tlo[o] = __float2bfloat16(v - __bfloat162float(h));
    }
}

// ---------------------------------------------------------------------------
// Softmax over 2048-wide rows; writes split-bf16 probs. grid=16384, block=256.
// ---------------------------------------------------------------------------
__global__ void softmax_split(const float* __restrict__ S, bf16* __restrict__ Ph,
                              bf16* __restrict__ Pl)
{
    __shared__ float red[8];
    const float* p = S + (size_t)blockIdx.x * 2048;
    const int t = threadIdx.x;

    float4 v0 = ((const float4*)p)[t];
    float4 v1 = ((const float4*)p)[t + 256];

    float m = fmaxf(fmaxf(fmaxf(v0.x, v0.y), fmaxf(v0.z, v0.w)),
                    fmaxf(fmaxf(v1.x, v1.y), fmaxf(v1.z, v1.w)));
#pragma unroll
    for (int o = 16; o; o >>= 1) m = fmaxf(m, __shfl_xor_sync(~0u, m, o));
    if ((t & 31) == 0) red[t >> 5] = m;
    __syncthreads();
    float mx = red[0];
#pragma unroll
    for (int w = 1; w < 8; w++) mx = fmaxf(mx, red[w]);
    __syncthreads();

    v0.x = __expf(v0.x - mx); v0.y = __expf(v0.y - mx);
    v0.z = __expf(v0.z - mx); v0.w = __expf(v0.w - mx);
    v1.x = __expf(v1.x - mx); v1.y = __expf(v1.y - mx);
    v1.z = __expf(v1.z - mx); v1.w = __expf(v1.w - mx);

    float s = v0.x + v0.y + v0.z + v0.w + v1.x + v1.y + v1.z + v1.w;
#pragma unroll
    for (int o = 16; o; o >>= 1) s += __shfl_xor_sync(~0u, s, o);
    if ((t & 31) == 0) red[t >> 5] = s;
    __syncthreads();
    float sm = 0.f;
#pragma unroll
    for (int w = 0; w < 8; w++) sm += red[w];
    const float inv = 1.f / sm;

    v0.x *= inv; v0.y *= inv; v0.z *= inv; v0.w *= inv;
    v1.x *= inv; v1.y *= inv; v1.z *= inv; v1.w *= inv;

    const size_t base = (size_t)blockIdx.x * 2048;
    ((uint2*)(Ph + base))[t] = make_uint2(pack_hi(v0.x, v0.y), pack_hi(v0.z, v0.w));
    ((uint2*)(Pl + base))[t] = make_uint2(pack_lo(v0.x, v0.y), pack_lo(v0.z, v0.w));
    ((uint2*)(Ph + base))[t + 256] = make_uint2(pack_hi(v1.x, v1.y), pack_hi(v1.z, v1.w));
    ((uint2*)(Pl + base))[t + 256] = make_uint2(pack_lo(v1.x, v1.y), pack_lo(v1.z, v1.w));
}

// ---------------------------------------------------------------------------
// BatchNorm stats (two-stage, deterministic) + combine epilogue
// ---------------------------------------------------------------------------
__global__ void bn_partial(const float* __restrict__ y, float* __restrict__ part)
{
    const int t = threadIdx.x;
    const float* base = y + (size_t)blockIdx.x * 128 * DD;
    float s[3] = {0.f, 0.f, 0.f}, q[3] = {0.f, 0.f, 0.f};
    for (int r = 0; r < 128; r++) {
        const float* row = base + (size_t)r * DD;
#pragma unroll
        for (int j = 0; j < 3; j++) {
            float v = row[t + j * 256];
            s[j] += v; q[j] += v * v;
        }
    }
#pragma unroll
    for (int j = 0; j < 3; j++) {
        part[blockIdx.x * DD + t + j * 256] = s[j];
        part[128 * DD + blockIdx.x * DD + t + j * 256] = q[j];
    }
}

__global__ void bn_finalize(const float* __restrict__ part,
                            const float* __restrict__ gamma,
                            const float* __restrict__ beta,
                            float* __restrict__ statsOut)
{
    const int c = blockIdx.x * 256 + threadIdx.x;
    float s = 0.f, q = 0.f;
    for (int k = 0; k < 128; k++) {
        s += part[k * DD + c];
        q += part[128 * DD + k * DD + c];
    }
    const float mean = s * (1.f / (float)MROWS);
    const float var  = q * (1.f / (float)MROWS) - mean * mean;
    const float scale = gamma[c] * rsqrtf(var + 1e-5f);
    statsOut[c]      = scale;
    statsOut[DD + c] = beta[c] - mean * scale;
}

__global__ void combine_ln(const float* __restrict__ x,
                           const float* __restrict__ ya,
                           const float* __restrict__ yv,
                           const float* __restrict__ stats,
                           const float* __restrict__ pa,
                           const float* __restrict__ pv,
                           const float* __restrict__ lng,
                           const float* __restrict__ lnb,
                           float* __restrict__ out)
{
    __shared__ float rs[8], rq[8];
    const int pos = blockIdx.x;
    const int b = pos >> 11, l = pos & 2047;
    const size_t yoff = (size_t)pos * DD;
    const size_t xoff = (size_t)l * (BB * DD) + (size_t)b * DD;
    const int t = threadIdx.x;
    const float aa = pa[0], av = pv[0];

    float vv[3];
    float s = 0.f, q = 0.f;
#pragma unroll
    for (int j = 0; j < 3; j++) {
        const int d = t + j * 256;
        float va = ya[yoff + d] * stats[d] + stats[DD + d];
        va = va > 0.f ? va : aa * va;
        float vb = yv[yoff + d] * stats[2 * DD + d] + stats[3 * DD + d];
        vb = vb > 0.f ? vb : av * vb;
        float val = x[xoff + d] + va + vb;
        vv[j] = val; s += val; q += val * val;
    }
#pragma unroll
    for (int o = 16; o; o >>= 1) {
        s += __shfl_xor_sync(~0u, s, o);
        q += __shfl_xor_sync(~0u, q, o);
    }
    if ((t & 31) == 0) { rs[t >> 5] = s; rq[t >> 5] = q; }
    __syncthreads();
    s = 0.f; q = 0.f;
#pragma unroll
    for (int w = 0; w < 8; w++) { s += rs[w]; q += rq[w]; }
    const float mean = s * (1.f / (float)DD);
    const float var  = q * (1.f / (float)DD) - mean * mean;
    const float rstd = rsqrtf(var + 1e-5f);
#pragma unroll
    for (int j = 0; j < 3; j++) {
        const int d = t + j * 256;
        out[xoff + d] = (vv[j] - mean) * rstd * lng[d] + lnb[d];
    }
}

// ---------------------------------------------------------------------------
// Host orchestration (graph-capturable)
// ---------------------------------------------------------------------------
extern "C" void kernel_launch(void* const* d_in, const int* in_sizes, int n_in,
                              void* d_out, int out_size)
{
    const float* x_a    = (const float*)d_in[0];
    const float* x_v    = (const float*)d_in[1];
    const float* x      = (const float*)d_in[2];
    const float* W_a    = (const float*)d_in[3];
    const float* bn_a_g = (const float*)d_in[5];
    const float* bn_a_b = (const float*)d_in[6];
    const float* pre_a  = (const float*)d_in[7];
    const float* W_v    = (const float*)d_in[8];
    const float* bn_v_g = (const float*)d_in[10];
    const float* bn_v_b = (const float*)d_in[11];
    const float* pre_v  = (const float*)d_in[12];
    const float* ln_g   = (const float*)d_in[13];
    const float* ln_b   = (const float*)d_in[14];
    float* out = (float*)d_out;

    float *S, *ya, *yv, *part, *stats;
    bf16 *Phi, *Plo, *qhi, *qlo, *kvhi, *kvlo, *kThi, *kTlo, *chi, *clo, *Whi, *Wlo;
    cudaGetSymbolAddress((void**)&S,    g_S);
    cudaGetSymbolAddress((void**)&Phi,  g_Phi);
    cudaGetSymbolAddress((void**)&Plo,  g_Plo);
    cudaGetSymbolAddress((void**)&qhi,  g_qhi);
    cudaGetSymbolAddress((void**)&qlo,  g_qlo);
    cudaGetSymbolAddress((void**)&kvhi, g_kvhi);
    cudaGetSymbolAddress((void**)&kvlo, g_kvlo);
    cudaGetSymbolAddress((void**)&kThi, g_kThi);
    cudaGetSymbolAddress((void**)&kTlo, g_kTlo);
    cudaGetSymbolAddress((void**)&chi,  g_chi);
    cudaGetSymbolAddress((void**)&clo,  g_clo);
    cudaGetSymbolAddress((void**)&Whi,  g_Whi);
    cudaGetSymbolAddress((void**)&Wlo,  g_Wlo);
    cudaGetSymbolAddress((void**)&ya,   g_ya);
    cudaGetSymbolAddress((void**)&yv,   g_yv);
    cudaGetSymbolAddress((void**)&part, g_part);
    cudaGetSymbolAddress((void**)&stats, g_stats);

    cudaFuncSetAttribute(mma_gemm<0>, cudaFuncAttributeMaxDynamicSharedMemorySize, GEMM_SMEM);
    cudaFuncSetAttribute(mma_gemm<1>, cudaFuncAttributeMaxDynamicSharedMemorySize, GEMM_SMEM);

    // q and W conversions (once)
    split_lbd_bld<<<dim3(LQ, BB), 256>>>(x, qhi, qlo);
    split_plain<<<(DD * DD) / 256, 256>>>(W_a, Whi, Wlo);
    split_plain<<<(DD * DD) / 256, 256>>>(W_v, Whi + DD * DD, Wlo + DD * DD);

    for (int br = 0; br < 2; br++) {
        const float* kv_src = (br == 0) ? x_a : x_v;
        const float* bng    = (br == 0) ? bn_a_g : bn_v_g;
        const float* bnb    = (br == 0) ? bn_a_b : bn_v_b;
        float*       y      = (br == 0) ? ya : yv;
        bf16*        wh     = Whi + br * DD * DD;
        bf16*        wl     = Wlo + br * DD * DD;
        float*       st     = stats + br * 2 * DD;

        split_lbd_bld<<<dim3(LQ, BB), 256>>>(kv_src, kvhi, kvlo);
        split_transpose<<<dim3(DD / 32, LQ / 32, BB), dim3(32, 8)>>>(kv_src, kThi, kTlo);

        // GEMM1: S[b,i,j] = scale * q[b,i,:] . kv[b,j,:]   (M=2048,N=2048,K=768)
        mma_gemm<0><<<dim3(16, 16, 8), 256, GEMM_SMEM>>>(
            qhi, qlo, kvhi, kvlo, S, nullptr, nullptr,
            DD, LQ, (long)LQ * DD, (long)LQ * DD, (long)LQ * LQ, QKSCALE);

        softmax_split<<<MROWS, 256>>>(S, Phi, Plo);

        // GEMM2: ctx[b,i,d] = P[b,i,:] . kvT[b,d,:]   (M=2048,N=768,K=2048)
        mma_gemm<1><<<dim3(6, 16, 8), 256, GEMM_SMEM>>>(
            Phi, Plo, kThi, kTlo, nullptr, chi, clo,
            LQ, DD, (long)LQ * LQ, (long)DD * LQ, (long)LQ * DD, 1.f);

        // GEMM3: y[r,e] = ctx[r,:] . W[e,:]   (M=16384,N=768,K=768), bias cancels in BN
        mma_gemm<0><<<dim3(6, 128, 1), 256, GEMM_SMEM>>>(
            chi, clo, wh, wl, y, nullptr, nullptr,
            DD, DD, 0, 0, 0, 1.f);

        bn_partial<<<128, 256>>>(y, part);
        bn_finalize<<<3, 256>>>(part, bng, bnb, st);
    }

    combine_ln<<<MROWS, 256>>>(x, ya, yv, stats, pre_a, pre_v, ln_g, ln_b, out);
}

// round 5
// speedup vs baseline: 3.2277x; 1.1059x over previous
#include <cuda_runtime.h>
#include <cuda_bf16.h>
#include <cstdint>

#define LQ 2048
#define BB 8
#define DD 768
#define MROWS (BB * LQ)
#define ZB (2 * BB)                 // branch*8 + batch
#define QKSCALE 0.0360843918243516f

using bf16 = __nv_bfloat16;

// ---------------------------------------------------------------------------
// Scratch (device globals; allocation-free per harness rules)
// ---------------------------------------------------------------------------
__device__ __align__(16) float g_S[(size_t)ZB * LQ * LQ];     // 256MB logits, both branches
__device__ __align__(16) bf16  g_Phi[(size_t)ZB * LQ * LQ];   // 128MB
__device__ __align__(16) bf16  g_Plo[(size_t)ZB * LQ * LQ];   // 128MB
__device__ __align__(16) bf16  g_qhi[(size_t)MROWS * DD], g_qlo[(size_t)MROWS * DD];
__device__ __align__(16) bf16  g_kvhi[(size_t)2 * MROWS * DD], g_kvlo[(size_t)2 * MROWS * DD];
__device__ __align__(16) bf16  g_kThi[(size_t)2 * MROWS * DD], g_kTlo[(size_t)2 * MROWS * DD];
__device__ __align__(16) bf16  g_chi[(size_t)2 * MROWS * DD], g_clo[(size_t)2 * MROWS * DD];
__device__ __align__(16) bf16  g_Whi[2 * DD * DD], g_Wlo[2 * DD * DD];
__device__ __align__(16) float g_y[(size_t)2 * MROWS * DD];   // conv out, both branches
__device__ float g_part[2 * 2 * 128 * DD];
__device__ float g_stats[2 * 2 * DD];

// ---------------------------------------------------------------------------
// Helpers (baseline PTX only: ldmatrix / mma.sync / cp.async)
// ---------------------------------------------------------------------------
__device__ __forceinline__ uint32_t smem_u32(const void* p) {
    uint32_t a;
    asm("{ .reg .u64 t; cvta.to.shared.u64 t, %1; cvt.u32.u64 %0, t; }" : "=r"(a) : "l"(p));
    return a;
}
__device__ __forceinline__ void cp16(uint32_t saddr, const void* gaddr) {
    asm volatile("cp.async.cg.shared.global [%0], [%1], 16;" :: "r"(saddr), "l"(gaddr));
}
#define CP_COMMIT() asm volatile("cp.async.commit_group;" ::: "memory")
#define CP_WAIT0()  asm volatile("cp.async.wait_group 0;" ::: "memory")
#define CP_WAIT1()  asm volatile("cp.async.wait_group 1;" ::: "memory")

__device__ __forceinline__ void ldmat_x4(uint32_t& r0, uint32_t& r1, uint32_t& r2,
                                         uint32_t& r3, uint32_t addr) {
    asm volatile("ldmatrix.sync.aligned.m8n8.x4.shared.b16 {%0,%1,%2,%3}, [%4];"
                 : "=r"(r0), "=r"(r1), "=r"(r2), "=r"(r3) : "r"(addr));
}
__device__ __forceinline__ void mma16816(float* c, uint32_t a0, uint32_t a1,
                                         uint32_t a2, uint32_t a3,
                                         uint32_t b0, uint32_t b1) {
    asm volatile(
        "mma.sync.aligned.m16n8k16.row.col.f32.bf16.bf16.f32 "
        "{%0,%1,%2,%3}, {%4,%5,%6,%7}, {%8,%9}, {%0,%1,%2,%3};"
        : "+f"(c[0]), "+f"(c[1]), "+f"(c[2]), "+f"(c[3])
        : "r"(a0), "r"(a1), "r"(a2), "r"(a3), "r"(b0), "r"(b1));
}

__device__ __forceinline__ uint32_t sw_off(int row, int kbyte) {
    uint32_t off = (uint32_t)row * 128u + (uint32_t)kbyte;
    return off ^ ((off >> 3) & 0x70u);
}
__device__ __forceinline__ void split1(float v, uint16_t& h, uint16_t& l) {
    bf16 hb = __float2bfloat16(v);
    h = __bfloat16_as_ushort(hb);
    l = __bfloat16_as_ushort(__float2bfloat16(v - __bfloat162float(hb)));
}
__device__ __forceinline__ uint32_t pack_hi(float a, float b) {
    uint16_t ha, la, hb, lb; split1(a, ha, la); split1(b, hb, lb);
    return (uint32_t)ha | ((uint32_t)hb << 16);
}
__device__ __forceinline__ uint32_t pack_lo(float a, float b) {
    uint16_t ha, la, hb, lb; split1(a, ha, la); split1(b, hb, lb);
    return (uint32_t)la | ((uint32_t)lb << 16);
}

// ---------------------------------------------------------------------------
// Split-bf16 warp-MMA GEMM: C[m,n] = alpha * sum_k A[m,k]*B[n,k]
// 128x128 tile, K in 64-chunks, 3-stage cp.async pipeline, 8 warps (64x32 each).
// A batch index = z & amask; B/C batch index = z.
// OUTMODE 0: fp32 C.  OUTMODE 1: split-bf16 C (Chi/Clo).
// ---------------------------------------------------------------------------
#define STAGE_BYTES 65536
#define GEMM_SMEM (3 * STAGE_BYTES)

__device__ __forceinline__ void stage_load(uint32_t sdst, const bf16* __restrict__ Ahi,
                                           const bf16* __restrict__ Alo,
                                           const bf16* __restrict__ Bhi,
                                           const bf16* __restrict__ Blo,
                                           int K, int k0, int t) {
#pragma unroll
    for (int i = 0; i < 4; i++) {
        int idx = t + i * 256;            // 0..1023
        int row = idx >> 3, ch = idx & 7; // 16B chunk in 128B row
        uint32_t so = sw_off(row, ch * 16);
        size_t go = (size_t)row * K + k0 + ch * 8;
        cp16(sdst + so,         Ahi + go);
        cp16(sdst + 16384 + so, Alo + go);
        cp16(sdst + 32768 + so, Bhi + go);
        cp16(sdst + 49152 + so, Blo + go);
    }
}

template<int OUTMODE>
__global__ void __launch_bounds__(256, 1)
mma_gemm(const bf16* __restrict__ Ahi, const bf16* __restrict__ Alo,
         const bf16* __restrict__ Bhi, const bf16* __restrict__ Blo,
         float* __restrict__ C, bf16* __restrict__ Chi, bf16* __restrict__ Clo,
         int K, int ldc, long sA, long sB, long sC, float alpha, int amask)
{
    extern __shared__ __align__(1024) char smem[];
    const uint32_t sb = smem_u32(smem);
    const int t = threadIdx.x, lane = t & 31, wid = t >> 5;
    const int wm = wid & 1, wn = wid >> 1;
    const int m0 = blockIdx.y * 128, n0 = blockIdx.x * 128, z = blockIdx.z;
    const int kiters = K >> 6;

    Ahi += (size_t)(z & amask) * sA + (size_t)m0 * K;
    Alo += (size_t)(z & amask) * sA + (size_t)m0 * K;
    Bhi += (size_t)z * sB + (size_t)n0 * K;
    Blo += (size_t)z * sB + (size_t)n0 * K;

    float acc[4][4][4];
#pragma unroll
    for (int i = 0; i < 4; i++)
#pragma unroll
        for (int j = 0; j < 4; j++)
#pragma unroll
            for (int q = 0; q < 4; q++) acc[i][j][q] = 0.f;

    // ldmatrix lane-address components
    const int a_m_add = (lane & 7) + ((lane >> 3) & 1) * 8;
    const int a_k_add = ((lane >> 4) & 1) * 8;
    // B x4: matrices (0,1) = n-tile +0 @ k 0/8; matrices (2,3) = n-tile +8 @ k 0/8
    const int b_n_add = (lane & 7) + ((lane >> 4) << 3);
    const int b_k_add = ((lane >> 3) & 1) * 8;

    stage_load(sb, Ahi, Alo, Bhi, Blo, K, 0, t);
    CP_COMMIT();
    if (kiters > 1) {
        stage_load(sb + STAGE_BYTES, Ahi, Alo, Bhi, Blo, K, 64, t);
        CP_COMMIT();
    }

    uint32_t cur = 0;  // rotating stage index
    for (int it = 0; it < kiters; it++) {
        if (it + 1 < kiters) { CP_WAIT1(); } else { CP_WAIT0(); }
        __syncthreads();
        if (it + 2 < kiters) {
            uint32_t nxt = cur + 2; if (nxt >= 3) nxt -= 3;
            stage_load(sb + nxt * STAGE_BYTES, Ahi, Alo, Bhi, Blo, K, (it + 2) << 6, t);
            CP_COMMIT();
        }
        const uint32_t st = sb + cur * STAGE_BYTES;

#pragma unroll
        for (int ks = 0; ks < 4; ks++) {
            const int kb = ks * 16;
            uint32_t ah[4][4], al[4][4];
#pragma unroll
            for (int tm = 0; tm < 4; tm++) {
                int m = wm * 64 + tm * 16 + a_m_add;
                uint32_t so = sw_off(m, (kb + a_k_add) * 2);
                ldmat_x4(ah[tm][0], ah[tm][1], ah[tm][2], ah[tm][3], st + so);
                ldmat_x4(al[tm][0], al[tm][1], al[tm][2], al[tm][3], st + 16384 + so);
            }
            uint32_t bh[4][2], bl[4][2];
#pragma unroll
            for (int tn2 = 0; tn2 < 2; tn2++) {
                int n = wn * 32 + tn2 * 16 + b_n_add;
                uint32_t so = sw_off(n, (kb + b_k_add) * 2);
                ldmat_x4(bh[tn2 * 2][0], bh[tn2 * 2][1],
                         bh[tn2 * 2 + 1][0], bh[tn2 * 2 + 1][1], st + 32768 + so);
                ldmat_x4(bl[tn2 * 2][0], bl[tn2 * 2][1],
                         bl[tn2 * 2 + 1][0], bl[tn2 * 2 + 1][1], st + 49152 + so);
            }
#pragma unroll
            for (int tm = 0; tm < 4; tm++)
#pragma unroll
                for (int tn = 0; tn < 4; tn++) {
                    mma16816(acc[tm][tn], ah[tm][0], ah[tm][1], ah[tm][2], ah[tm][3],
                             bh[tn][0], bh[tn][1]);
                    mma16816(acc[tm][tn], ah[tm][0], ah[tm][1], ah[tm][2], ah[tm][3],
                             bl[tn][0], bl[tn][1]);
                    mma16816(acc[tm][tn], al[tm][0], al[tm][1], al[tm][2], al[tm][3],
                             bh[tn][0], bh[tn][1]);
                }
        }
        cur = cur + 1; if (cur >= 3) cur -= 3;
    }

    // Epilogue
    const int gid = lane >> 2, tig = lane & 3;
#pragma unroll
    for (int tm = 0; tm < 4; tm++) {
        const int r0 = m0 + wm * 64 + tm * 16 + gid;
#pragma unroll
        for (int tn = 0; tn < 4; tn++) {
            const int cN = n0 + wn * 32 + tn * 8 + tig * 2;
            float* a = acc[tm][tn];
            if (OUTMODE == 0) {
                *(float2*)(C + (size_t)z * sC + (size_t)r0 * ldc + cN) =
                    make_float2(a[0] * alpha, a[1] * alpha);
                *(float2*)(C + (size_t)z * sC + (size_t)(r0 + 8) * ldc + cN) =
                    make_float2(a[2] * alpha, a[3] * alpha);
            } else {
                *(uint32_t*)(Chi + (size_t)z * sC + (size_t)r0 * ldc + cN) = pack_hi(a[0], a[1]);
                *(uint32_t*)(Clo + (size_t)z * sC + (size_t)r0 * ldc + cN) = pack_lo(a[0], a[1]);
                *(uint32_t*)(Chi + (size_t)z * sC + (size_t)(r0 + 8) * ldc + cN) = pack_hi(a[2], a[3]);
                *(uint32_t*)(Clo + (size_t)z * sC + (size_t)(r0 + 8) * ldc + cN) = pack_lo(a[2], a[3]);
            }
        }
    }
}

// ---------------------------------------------------------------------------
// Prep kernels
// ---------------------------------------------------------------------------
// x [L,B,D] -> q split [B,L,D]
__global__ void split_q(const float* __restrict__ in, bf16* __restrict__ hi,
                        bf16* __restrict__ lo)
{
    const int l = blockIdx.x, b = blockIdx.y, t = threadIdx.x;
    const float* s = in + (size_t)l * (BB * DD) + (size_t)b * DD;
    const size_t o = ((size_t)b * LQ + l) * DD;
#pragma unroll
    for (int j = 0; j < 3; j++) {
        float v = s[t + j * 256];
        bf16 h = __float2bfloat16(v);
        hi[o + t + j * 256] = h;
        lo[o + t + j * 256] = __float2bfloat16(v - __bfloat162float(h));
    }
}

// W_a/W_v -> split (both branches, z picks source)
__global__ void split_w(const float* __restrict__ wa, const float* __restrict__ wv,
                        bf16* __restrict__ hi, bf16* __restrict__ lo)
{
    const int br = blockIdx.y;
    const int i = blockIdx.x * 256 + threadIdx.x;
    float v = (br ? wv : wa)[i];
    bf16 h = __float2bfloat16(v);
    hi[br * DD * DD + i] = h;
    lo[br * DD * DD + i] = __float2bfloat16(v - __bfloat162float(h));
}

// x_a/x_v [L,B,D] -> kv split [z][L][D] AND kvT split [z][D][L], z = br*8+b
__global__ void prep_kv(const float* __restrict__ xa, const float* __restrict__ xv,
                        bf16* __restrict__ kvhi, bf16* __restrict__ kvlo,
                        bf16* __restrict__ thi, bf16* __restrict__ tlo)
{
    __shared__ uint16_t th[32][33], tl[32][33];
    const int z = blockIdx.z, b = z & 7;
    const float* src = (z >> 3) ? xv : xa;
    const int d0 = blockIdx.x * 32, l0 = blockIdx.y * 32;
    const int tx = threadIdx.x, ty = threadIdx.y;
#pragma unroll
    for (int r = 0; r < 4; r++) {
        int l = l0 + ty + r * 8;
        float v = src[(size_t)l * (BB * DD) + (size_t)b * DD + d0 + tx];
        uint16_t h, lw; split1(v, h, lw);
        size_t o = ((size_t)z * LQ + l) * DD + d0 + tx;
        kvhi[o] = __ushort_as_bfloat16(h);
        kvlo[o] = __ushort_as_bfloat16(lw);
        th[ty + r * 8][tx] = h;
        tl[ty + r * 8][tx] = lw;
    }
    __syncthreads();
#pragma unroll
    for (int r = 0; r < 4; r++) {
        int d = d0 + ty + r * 8;
        size_t o = ((size_t)z * DD + d) * LQ + l0 + tx;
        thi[o] = __ushort_as_bfloat16(th[tx][ty + r * 8]);
        tlo[o] = __ushort_as_bfloat16(tl[tx][ty + r * 8]);
    }
}

// ---------------------------------------------------------------------------
// Softmax over 2048-wide rows -> split bf16. grid = ZB*LQ, block = 256.
// ---------------------------------------------------------------------------
__global__ void softmax_split(const float* __restrict__ S, bf16* __restrict__ Ph,
                              bf16* __restrict__ Pl)
{
    __shared__ float red[8];
    const float* p = S + (size_t)blockIdx.x * 2048;
    const int t = threadIdx.x;

    float4 v0 = ((const float4*)p)[t];
    float4 v1 = ((const float4*)p)[t + 256];

    float m = fmaxf(fmaxf(fmaxf(v0.x, v0.y), fmaxf(v0.z, v0.w)),
                    fmaxf(fmaxf(v1.x, v1.y), fmaxf(v1.z, v1.w)));
#pragma unroll
    for (int o = 16; o; o >>= 1) m = fmaxf(m, __shfl_xor_sync(~0u, m, o));
    if ((t & 31) == 0) red[t >> 5] = m;
    __syncthreads();
    float mx = red[0];
#pragma unroll
    for (int w = 1; w < 8; w++) mx = fmaxf(mx, red[w]);
    __syncthreads();

    v0.x = __expf(v0.x - mx); v0.y = __expf(v0.y - mx);
    v0.z = __expf(v0.z - mx); v0.w = __expf(v0.w - mx);
    v1.x = __expf(v1.x - mx); v1.y = __expf(v1.y - mx);
    v1.z = __expf(v1.z - mx); v1.w = __expf(v1.w - mx);

    float s = v0.x + v0.y + v0.z + v0.w + v1.x + v1.y + v1.z + v1.w;
#pragma unroll
    for (int o = 16; o; o >>= 1) s += __shfl_xor_sync(~0u, s, o);
    if ((t & 31) == 0) red[t >> 5] = s;
    __syncthreads();
    float sm = 0.f;
#pragma unroll
    for (int w = 0; w < 8; w++) sm += red[w];
    const float inv = 1.f / sm;

    v0.x *= inv; v0.y *= inv; v0.z *= inv; v0.w *= inv;
    v1.x *= inv; v1.y *= inv; v1.z *= inv; v1.w *= inv;

    const size_t base = (size_t)blockIdx.x * 2048;
    ((uint2*)(Ph + base))[t] = make_uint2(pack_hi(v0.x, v0.y), pack_hi(v0.z, v0.w));
    ((uint2*)(Pl + base))[t] = make_uint2(pack_lo(v0.x, v0.y), pack_lo(v0.z, v0.w));
    ((uint2*)(Ph + base))[t + 256] = make_uint2(pack_hi(v1.x, v1.y), pack_hi(v1.z, v1.w));
    ((uint2*)(Pl + base))[t + 256] = make_uint2(pack_lo(v1.x, v1.y), pack_lo(v1.z, v1.w));
}

// ---------------------------------------------------------------------------
// BatchNorm stats (two-stage, deterministic; grid.y = branch)
// ---------------------------------------------------------------------------
__global__ void bn_partial(const float* __restrict__ yAll, float* __restrict__ partAll)
{
    const int br = blockIdx.y, t = threadIdx.x;
    const float* base = yAll + (size_t)br * MROWS * DD + (size_t)blockIdx.x * 128 * DD;
    float* part = partAll + (size_t)br * 2 * 128 * DD;
    float s[3] = {0.f, 0.f, 0.f}, q[3] = {0.f, 0.f, 0.f};
    for (int r = 0; r < 128; r++) {
        const float* row = base + (size_t)r * DD;
#pragma unroll
        for (int j = 0; j < 3; j++) {
            float v = row[t + j * 256];
            s[j] += v; q[j] += v * v;
        }
    }
#pragma unroll
    for (int j = 0; j < 3; j++) {
        part[blockIdx.x * DD + t + j * 256] = s[j];
        part[128 * DD + blockIdx.x * DD + t + j * 256] = q[j];
    }
}

__global__ void bn_finalize(const float* __restrict__ partAll,
                            const float* __restrict__ ga, const float* __restrict__ ba,
                            const float* __restrict__ gv, const float* __restrict__ bv,
                            float* __restrict__ statsAll)
{
    const int br = blockIdx.y;
    const int c = blockIdx.x * 256 + threadIdx.x;
    const float* part = partAll + (size_t)br * 2 * 128 * DD;
    const float* gamma = br ? gv : ga;
    const float* beta  = br ? bv : ba;
    float* statsOut = statsAll + br * 2 * DD;
    float s = 0.f, q = 0.f;
    for (int k = 0; k < 128; k++) {
        s += part[k * DD + c];
        q += part[128 * DD + k * DD + c];
    }
    const float mean = s * (1.f / (float)MROWS);
    const float var  = q * (1.f / (float)MROWS) - mean * mean;
    const float scale = gamma[c] * rsqrtf(var + 1e-5f);
    statsOut[c]      = scale;
    statsOut[DD + c] = beta[c] - mean * scale;
}

// ---------------------------------------------------------------------------
// Combine: BN-apply + PReLU + residual + LayerNorm. grid = MROWS.
// ---------------------------------------------------------------------------
__global__ void combine_ln(const float* __restrict__ x,
                           const float* __restrict__ yAll,
                           const float* __restrict__ stats,
                           const float* __restrict__ pa,
                           const float* __restrict__ pv,
                           const float* __restrict__ lng,
                           const float* __restrict__ lnb,
                           float* __restrict__ out)
{
    __shared__ float rs[8], rq[8];
    const int pos = blockIdx.x;
    const int b = pos >> 11, l = pos & 2047;
    const size_t yoff = (size_t)pos * DD;
    const size_t xoff = (size_t)l * (BB * DD) + (size_t)b * DD;
    const int t = threadIdx.x;
    const float aa = pa[0], av = pv[0];
    const float* ya = yAll;
    const float* yv = yAll + (size_t)MROWS * DD;

    float vv[3];
    float s = 0.f, q = 0.f;
#pragma unroll
    for (int j = 0; j < 3; j++) {
        const int d = t + j * 256;
        float va = ya[yoff + d] * stats[d] + stats[DD + d];
        va = va > 0.f ? va : aa * va;
        float vb = yv[yoff + d] * stats[2 * DD + d] + stats[3 * DD + d];
        vb = vb > 0.f ? vb : av * vb;
        float val = x[xoff + d] + va + vb;
        vv[j] = val; s += val; q += val * val;
    }
#pragma unroll
    for (int o = 16; o; o >>= 1) {
        s += __shfl_xor_sync(~0u, s, o);
        q += __shfl_xor_sync(~0u, q, o);
    }
    if ((t & 31) == 0) { rs[t >> 5] = s; rq[t >> 5] = q; }
    __syncthreads();
    s = 0.f; q = 0.f;
#pragma unroll
    for (int w = 0; w < 8; w++) { s += rs[w]; q += rq[w]; }
    const float mean = s * (1.f / (float)DD);
    const float var  = q * (1.f / (float)DD) - mean * mean;
    const float rstd = rsqrtf(var + 1e-5f);
#pragma unroll
    for (int j = 0; j < 3; j++) {
        const int d = t + j * 256;
        out[xoff + d] = (vv[j] - mean) * rstd * lng[d] + lnb[d];
    }
}

// ---------------------------------------------------------------------------
// Host orchestration (graph-capturable)
// ---------------------------------------------------------------------------
extern "C" void kernel_launch(void* const* d_in, const int* in_sizes, int n_in,
                              void* d_out, int out_size)
{
    const float* x_a    = (const float*)d_in[0];
    const float* x_v    = (const float*)d_in[1];
    const float* x      = (const float*)d_in[2];
    const float* W_a    = (const float*)d_in[3];
    const float* bn_a_g = (const float*)d_in[5];
    const float* bn_a_b = (const float*)d_in[6];
    const float* pre_a  = (const float*)d_in[7];
    const float* W_v    = (const float*)d_in[8];
    const float* bn_v_g = (const float*)d_in[10];
    const float* bn_v_b = (const float*)d_in[11];
    const float* pre_v  = (const float*)d_in[12];
    const float* ln_g   = (const float*)d_in[13];
    const float* ln_b   = (const float*)d_in[14];
    float* out = (float*)d_out;

    float *S, *y, *part, *stats;
    bf16 *Phi, *Plo, *qhi, *qlo, *kvhi, *kvlo, *kThi, *kTlo, *chi, *clo, *Whi, *Wlo;
    cudaGetSymbolAddress((void**)&S,    g_S);
    cudaGetSymbolAddress((void**)&Phi,  g_Phi);
    cudaGetSymbolAddress((void**)&Plo,  g_Plo);
    cudaGetSymbolAddress((void**)&qhi,  g_qhi);
    cudaGetSymbolAddress((void**)&qlo,  g_qlo);
    cudaGetSymbolAddress((void**)&kvhi, g_kvhi);
    cudaGetSymbolAddress((void**)&kvlo, g_kvlo);
    cudaGetSymbolAddress((void**)&kThi, g_kThi);
    cudaGetSymbolAddress((void**)&kTlo, g_kTlo);
    cudaGetSymbolAddress((void**)&chi,  g_chi);
    cudaGetSymbolAddress((void**)&clo,  g_clo);
    cudaGetSymbolAddress((void**)&Whi,  g_Whi);
    cudaGetSymbolAddress((void**)&Wlo,  g_Wlo);
    cudaGetSymbolAddress((void**)&y,    g_y);
    cudaGetSymbolAddress((void**)&part, g_part);
    cudaGetSymbolAddress((void**)&stats, g_stats);

    cudaFuncSetAttribute(mma_gemm<0>, cudaFuncAttributeMaxDynamicSharedMemorySize, GEMM_SMEM);
    cudaFuncSetAttribute(mma_gemm<1>, cudaFuncAttributeMaxDynamicSharedMemorySize, GEMM_SMEM);

    // Prep: q, W, kv/kvT (both branches each)
    split_q<<<dim3(LQ, BB), 256>>>(x, qhi, qlo);
    split_w<<<dim3((DD * DD) / 256, 2), 256>>>(W_a, W_v, Whi, Wlo);
    prep_kv<<<dim3(DD / 32, LQ / 32, ZB), dim3(32, 8)>>>(x_a, x_v, kvhi, kvlo, kThi, kTlo);

    // GEMM1: S[z,i,j] = scale * q[z&7,i,:].kv[z,j,:]  (M=2048,N=2048,K=768, z=16)
    mma_gemm<0><<<dim3(16, 16, ZB), 256, GEMM_SMEM>>>(
        qhi, qlo, kvhi, kvlo, S, nullptr, nullptr,
        DD, LQ, (long)LQ * DD, (long)LQ * DD, (long)LQ * LQ, QKSCALE, 7);

    softmax_split<<<ZB * LQ, 256>>>(S, Phi, Plo);

    // GEMM2: ctx[z,i,d] = P[z,i,:].kvT[z,d,:]  (M=2048,N=768,K=2048, z=16)
    mma_gemm<1><<<dim3(6, 16, ZB), 256, GEMM_SMEM>>>(
        Phi, Plo, kThi, kTlo, nullptr, chi, clo,
        LQ, DD, (long)LQ * LQ, (long)DD * LQ, (long)LQ * DD, 1.f, 0xFF);

    // GEMM3: y[br,r,e] = ctx[br,r,:].W[br,e,:]  (M=16384,N=768,K=768, z=2)
    mma_gemm<0><<<dim3(6, 128, 2), 256, GEMM_SMEM>>>(
        chi, clo, Whi, Wlo, y, nullptr, nullptr,
        DD, DD, (long)MROWS * DD, (long)DD * DD, (long)MROWS * DD, 1.f, 0xFF);

    bn_partial<<<dim3(128, 2), 256>>>(y, part);
    bn_finalize<<<dim3(3, 2), 256>>>(part, bn_a_g, bn_a_b, bn_v_g, bn_v_b, stats);

    combine_ln<<<MROWS, 256>>>(x, y, stats, pre_a, pre_v, ln_g, ln_b, out);
}